// round 16
// baseline (speedup 1.0000x reference)
#include <cuda_runtime.h>
#include <cuda_bf16.h>
#include <stdint.h>
#include <math.h>

#define T_FRAMES 8
#define C_DIM    256
#define HW       4096
#define EPS      1e-8f
#define INV_TEMP (1.0f/0.07f)

// ---------------- device scratch (static, zero-init at load) ----------------
__device__ int   g_nfg[T_FRAMES];
__device__ int   g_nbg[T_FRAMES];
__device__ int   g_use[T_FRAMES];
__device__ __nv_bfloat16 g_fgH[T_FRAMES][HW][C_DIM];  // row-major compacted normalized fg
__device__ __nv_bfloat16 g_bgH[T_FRAMES][HW][C_DIM];  // row-major compacted normalized bg
__device__ float g_neg[T_FRAMES][HW];
__device__ float g_frame[T_FRAMES];
__device__ float g_validf[T_FRAMES];
__device__ int   g_done;

#define CP_ASYNC16(dst, src) \
    asm volatile("cp.async.cg.shared.global [%0], [%1], 16;" :: "r"(dst), "l"(src))
#define CP_COMMIT() asm volatile("cp.async.commit_group;" ::: "memory")
#define CP_WAIT1()  asm volatile("cp.async.wait_group 1;" ::: "memory")
#define CP_WAIT0()  asm volatile("cp.async.wait_group 0;" ::: "memory")

// gemm smem geometry: 3 stages x 128 rows x 72 bf16 (144B rows, odd 16B phase)
#define GROW   72
#define GSTG   (128 * GROW)                  // elements per stage per array
#define GEMM_SMEM (3 * GSTG * 2 * 2)         // bytes: 3 stages, A+B, bf16

// ---------------- K1: per-frame dice deviation -> use_curr flag ----------------
__global__ void k_counts(const float* __restrict__ cur,
                         const float* __restrict__ hist)
{
    int t = blockIdx.x, tid = threadIdx.x;
    __shared__ int s1[256], s2[256], s3[256];
    const float* cp = cur  + t * HW;
    const float* hp = hist + t * HW;
    int c1 = 0, c2 = 0, c3 = 0;
    for (int n = tid; n < HW; n += 256) {
        int cb = cp[n] > 0.5f;
        int hb = hp[n] > 0.5f;
        c1 += cb & hb; c2 += cb; c3 += hb;
    }
    s1[tid] = c1; s2[tid] = c2; s3[tid] = c3;
    __syncthreads();
    for (int off = 128; off > 0; off >>= 1) {
        if (tid < off) { s1[tid] += s1[tid+off]; s2[tid] += s2[tid+off]; s3[tid] += s3[tid+off]; }
        __syncthreads();
    }
    if (tid == 0) {
        float e1 = (float)s1[0];
        float e2 = (float)s2[0] + (float)s3[0];
        float m1 = (2.0f * e1 + EPS) / (e2 + EPS);
        float m2 = (e1 + EPS) / (e2 - e1 + EPS);
        float dev = 1.0f - (m1 + m2) * 0.5f;
        g_use[t] = (dev <= 0.0f) ? 1 : 0;
        g_nfg[t] = 0;
        g_nbg[t] = 0;
    }
}

// ---------------- K2: fused labels + pos-assign + neg-zero + norm + gather ----------------
// grid (HW/32, T), block (32, 8)
__global__ __launch_bounds__(256) void k_preprocess(const float* __restrict__ cur,
                                                    const float* __restrict__ hist,
                                                    const float* __restrict__ feat,
                                                    float* __restrict__ out)
{
    __shared__ float sf[32][260];
    __shared__ float ssp[8][32];
    __shared__ float sinv[32];
    __shared__ int   s_pos[32];
    int n0 = blockIdx.x * 32, t = blockIdx.y;
    int x = threadIdx.x, y = threadIdx.y;

    if (y == 0) {
        int n = n0 + x;
        float l = g_use[t] ? cur[t * HW + n] : hist[t * HW + n];
        out[t * HW + n] = l;
        g_neg[t][n] = 0.0f;
        int pp;
        if (l > 0.5f) pp = atomicAdd(&g_nfg[t], 1);
        else          pp = ~atomicAdd(&g_nbg[t], 1);
        s_pos[x] = pp;
    }

    const float* base = feat + (size_t)t * C_DIM * HW + n0 + x;
    float ss = 0.0f;
    #pragma unroll
    for (int cs = 0; cs < 32; cs++) {
        int c = y + cs * 8;
        float v = base[(size_t)c * HW];
        sf[x][c] = v;
        ss = fmaf(v, v, ss);
    }
    ssp[y][x] = ss;
    __syncthreads();
    if (y == 0) {
        float s = 0.0f;
        #pragma unroll
        for (int i = 0; i < 8; i++) s += ssp[i][x];
        sinv[x] = 1.0f / fmaxf(sqrtf(s), 1e-12f);
    }
    __syncthreads();

    int w = y * 32 + x;
    int nl = w >> 3, part = w & 7;
    int pp = s_pos[nl];
    __nv_bfloat16* dst = (pp >= 0) ? &g_fgH[t][pp][0] : &g_bgH[t][~pp][0];
    float inv = sinv[nl];
    #pragma unroll
    for (int q = 0; q < 4; q++) {
        int c = part * 32 + q * 8;
        float4 v0 = *(const float4*)&sf[nl][c];
        float4 v1 = *(const float4*)&sf[nl][c + 4];
        __nv_bfloat16 v[8];
        v[0] = __float2bfloat16(v0.x * inv); v[1] = __float2bfloat16(v0.y * inv);
        v[2] = __float2bfloat16(v0.z * inv); v[3] = __float2bfloat16(v0.w * inv);
        v[4] = __float2bfloat16(v1.x * inv); v[5] = __float2bfloat16(v1.y * inv);
        v[6] = __float2bfloat16(v1.z * inv); v[7] = __float2bfloat16(v1.w * inv);
        *(uint4*)&dst[c] = *(uint4*)v;
    }
}

// ---------------- K3 (launch 3): reset scratch for fused tail ----------------
__global__ void k_reset()
{
    if (blockIdx.x == 0 && threadIdx.x == 0) g_done = 0;
    if (threadIdx.x < T_FRAMES && blockIdx.x == 0) {
        g_frame[threadIdx.x]  = 0.0f;
        g_validf[threadIdx.x] = 0.0f;
    }
}

// ---------------- K4 (launch 4 -> ncu): bf16 mma GEMM, 128x128, K-chunk 64, 3-stage ----------------
__global__ __launch_bounds__(256, 2) void k_gemm()
{
    extern __shared__ __align__(16) char dsm[];
    __nv_bfloat16 (*As)[128][GROW] = (__nv_bfloat16 (*)[128][GROW])dsm;
    __nv_bfloat16 (*Bs)[128][GROW] = (__nv_bfloat16 (*)[128][GROW])(dsm + 3 * GSTG * 2);

    int t = blockIdx.z;
    int nfg = g_nfg[t], nbg = g_nbg[t];
    int i0 = blockIdx.y * 128;
    int j0 = blockIdx.x * 128;
    if (i0 >= nfg || j0 >= nbg) return;

    const __nv_bfloat16* A = &g_fgH[t][0][0];
    const __nv_bfloat16* B = &g_bgH[t][0][0];

    int tid = threadIdx.x;
    int lane = tid & 31, wid = tid >> 5;
    int wrow = wid >> 2, wcol = wid & 3;     // 2 (m) x 4 (n) warps, 64x32 each
    int srow = tid >> 1;                     // 0..127
    int scolB = (tid & 1) * 64;              // byte offset in 128B chunk-row

    float acc[4][4][4] = {};

    // copy one 64-col chunk (128B/row) for A and B into stage s
    auto issue = [&](int ch, int s) {
        int k0 = ch * 64;
        const char* srcA = (const char*)&A[(size_t)(i0 + srow) * C_DIM + k0] + scolB;
        const char* srcB = (const char*)&B[(size_t)(j0 + srow) * C_DIM + k0] + scolB;
        uint32_t da = (uint32_t)__cvta_generic_to_shared((char*)&As[s][srow][0] + scolB);
        uint32_t db = (uint32_t)__cvta_generic_to_shared((char*)&Bs[s][srow][0] + scolB);
        #pragma unroll
        for (int u = 0; u < 4; u++) {
            CP_ASYNC16(da + u * 16, srcA + u * 16);
            CP_ASYNC16(db + u * 16, srcB + u * 16);
        }
        CP_COMMIT();
    };

    issue(0, 0);
    issue(1, 1);

    #pragma unroll
    for (int ch = 0; ch < 4; ch++) {
        if (ch < 2) CP_WAIT1(); else CP_WAIT0();
        __syncthreads();
        if (ch + 2 < 4) issue(ch + 2, (ch + 2) % 3);

        int buf = ch % 3;
        #pragma unroll
        for (int ks = 0; ks < 64; ks += 16) {
            uint32_t bfr[4][2];
            #pragma unroll
            for (int p = 0; p < 2; p++) {
                int grp = lane >> 3;
                int nrow = wcol * 32 + p * 16 + ((grp >> 1) << 3) + (lane & 7);
                int ncol = ks + ((grp & 1) << 3);
                uint32_t addr = (uint32_t)__cvta_generic_to_shared(&Bs[buf][nrow][ncol]);
                asm volatile("ldmatrix.sync.aligned.m8n8.x4.shared.b16 {%0,%1,%2,%3}, [%4];"
                    : "=r"(bfr[2*p][0]), "=r"(bfr[2*p][1]),
                      "=r"(bfr[2*p+1][0]), "=r"(bfr[2*p+1][1]) : "r"(addr));
            }
            #pragma unroll
            for (int mt = 0; mt < 4; mt++) {
                int mrow = wrow * 64 + mt * 16 + (lane & 7) + ((lane >> 3) & 1) * 8;
                int mcol = ks + (lane >> 4) * 8;
                uint32_t addr = (uint32_t)__cvta_generic_to_shared(&As[buf][mrow][mcol]);
                uint32_t af[4];
                asm volatile("ldmatrix.sync.aligned.m8n8.x4.shared.b16 {%0,%1,%2,%3}, [%4];"
                    : "=r"(af[0]), "=r"(af[1]), "=r"(af[2]), "=r"(af[3]) : "r"(addr));
                #pragma unroll
                for (int nt = 0; nt < 4; nt++) {
                    asm volatile(
                        "mma.sync.aligned.m16n8k16.row.col.f32.bf16.bf16.f32 "
                        "{%0,%1,%2,%3}, {%4,%5,%6,%7}, {%8,%9}, {%0,%1,%2,%3};"
                        : "+f"(acc[mt][nt][0]), "+f"(acc[mt][nt][1]),
                          "+f"(acc[mt][nt][2]), "+f"(acc[mt][nt][3])
                        : "r"(af[0]), "r"(af[1]), "r"(af[2]), "r"(af[3]),
                          "r"(bfr[nt][0]), "r"(bfr[nt][1]));
                }
            }
        }
        __syncthreads();
    }

    // epilogue: exp + masked row sums
    int g = lane >> 2, tg = lane & 3;
    #pragma unroll
    for (int mt = 0; mt < 4; mt++) {
        float slo = 0.0f, shi = 0.0f;
        #pragma unroll
        for (int nt = 0; nt < 4; nt++) {
            int jb = j0 + wcol * 32 + nt * 8 + 2 * tg;
            if (jb < nbg)     { slo += __expf(acc[mt][nt][0] * INV_TEMP);
                                shi += __expf(acc[mt][nt][2] * INV_TEMP); }
            if (jb + 1 < nbg) { slo += __expf(acc[mt][nt][1] * INV_TEMP);
                                shi += __expf(acc[mt][nt][3] * INV_TEMP); }
        }
        slo += __shfl_xor_sync(0xffffffffu, slo, 1);
        slo += __shfl_xor_sync(0xffffffffu, slo, 2);
        shi += __shfl_xor_sync(0xffffffffu, shi, 1);
        shi += __shfl_xor_sync(0xffffffffu, shi, 2);
        if (tg == 0) {
            int i = i0 + wrow * 64 + mt * 16 + g;
            if (i < nfg)     atomicAdd(&g_neg[t][i], slo);
            if (i + 8 < nfg) atomicAdd(&g_neg[t][i + 8], shi);
        }
    }
}

// ---------------- K5: fused per-frame loss + final reduction ----------------
__global__ void k_tail(float* __restrict__ out, int loss_pos)
{
    int t = blockIdx.x, tid = threadIdx.x;
    int nfg = g_nfg[t], nbg = g_nbg[t];
    const float POS_INV = expf(-INV_TEMP);
    float local = 0.0f;
    for (int i = tid; i < nfg; i += 256)
        local += log1pf((g_neg[t][i] + EPS) * POS_INV);
    __shared__ float sh[256];
    sh[tid] = local;
    __syncthreads();
    for (int off = 128; off > 0; off >>= 1) {
        if (tid < off) sh[tid] += sh[tid + off];
        __syncthreads();
    }
    __shared__ int s_last;
    if (tid == 0) {
        float fl = sh[0] / fmaxf((float)nfg, 1.0f);
        int valid = (nfg > 0 && nbg > 0) ? 1 : 0;
        g_frame[t]  = valid ? fl : 0.0f;
        g_validf[t] = (float)valid;
        __threadfence();
        s_last = (atomicAdd(&g_done, 1) == T_FRAMES - 1);
    }
    __syncthreads();
    if (s_last && tid == 0) {
        float s = 0.0f, nv = 0.0f;
        for (int u = 0; u < T_FRAMES; u++) { s += g_frame[u]; nv += g_validf[u]; }
        out[loss_pos] = (nv > 0.0f) ? (s / fmaxf(nv, 1.0f)) : 0.0f;
    }
}

// ---------------- launch ----------------
extern "C" void kernel_launch(void* const* d_in, const int* in_sizes, int n_in,
                              void* d_out, int out_size)
{
    const float* cur  = (const float*)d_in[0];
    const float* hist = (const float*)d_in[1];
    const float* feat = (const float*)d_in[2];
    float* out = (float*)d_out;

    cudaFuncSetAttribute(k_gemm, cudaFuncAttributeMaxDynamicSharedMemorySize, GEMM_SMEM);

    k_counts<<<T_FRAMES, 256>>>(cur, hist);                                       // launch 1
    k_preprocess<<<dim3(HW / 32, T_FRAMES), dim3(32, 8)>>>(cur, hist, feat, out); // launch 2
    k_reset<<<1, 32>>>();                                                         // launch 3
    k_gemm<<<dim3(HW / 128, HW / 128, T_FRAMES), 256, GEMM_SMEM>>>();             // launch 4 (ncu)
    k_tail<<<T_FRAMES, 256>>>(out, out_size - 1);                                 // launch 5
}

// round 17
// speedup vs baseline: 1.1963x; 1.1963x over previous
#include <cuda_runtime.h>
#include <cuda_bf16.h>
#include <stdint.h>
#include <math.h>

#define T_FRAMES 8
#define C_DIM    256
#define HW       4096
#define EPS      1e-8f
#define INV_TEMP (1.0f/0.07f)

// ---------------- device scratch (static, zero-init at load) ----------------
__device__ int   g_nfg[T_FRAMES];
__device__ int   g_nbg[T_FRAMES];
__device__ int   g_use[T_FRAMES];
__device__ __nv_bfloat16 g_fgH[T_FRAMES][HW][C_DIM];  // row-major compacted normalized fg
__device__ __nv_bfloat16 g_bgH[T_FRAMES][HW][C_DIM];  // row-major compacted normalized bg
__device__ float g_neg[T_FRAMES][HW];
__device__ float g_frame[T_FRAMES];
__device__ float g_validf[T_FRAMES];
__device__ int   g_done;

#define CP_ASYNC16(dst, src) \
    asm volatile("cp.async.cg.shared.global [%0], [%1], 16;" :: "r"(dst), "l"(src))
#define CP_COMMIT() asm volatile("cp.async.commit_group;" ::: "memory")
#define CP_WAIT1()  asm volatile("cp.async.wait_group 1;" ::: "memory")
#define CP_WAIT0()  asm volatile("cp.async.wait_group 0;" ::: "memory")

// ---------------- K1: per-frame dice deviation -> use flag; also reset tail scratch ----------------
__global__ void k_counts(const float* __restrict__ cur,
                         const float* __restrict__ hist)
{
    int t = blockIdx.x, tid = threadIdx.x;
    if (t == 0 && tid == 0) g_done = 0;
    if (t == 0 && tid < T_FRAMES) { g_frame[tid] = 0.0f; g_validf[tid] = 0.0f; }
    __shared__ int s1[256], s2[256], s3[256];
    const float* cp = cur  + t * HW;
    const float* hp = hist + t * HW;
    int c1 = 0, c2 = 0, c3 = 0;
    for (int n = tid; n < HW; n += 256) {
        int cb = cp[n] > 0.5f;
        int hb = hp[n] > 0.5f;
        c1 += cb & hb; c2 += cb; c3 += hb;
    }
    s1[tid] = c1; s2[tid] = c2; s3[tid] = c3;
    __syncthreads();
    for (int off = 128; off > 0; off >>= 1) {
        if (tid < off) { s1[tid] += s1[tid+off]; s2[tid] += s2[tid+off]; s3[tid] += s3[tid+off]; }
        __syncthreads();
    }
    if (tid == 0) {
        float e1 = (float)s1[0];
        float e2 = (float)s2[0] + (float)s3[0];
        float m1 = (2.0f * e1 + EPS) / (e2 + EPS);
        float m2 = (e1 + EPS) / (e2 - e1 + EPS);
        float dev = 1.0f - (m1 + m2) * 0.5f;
        g_use[t] = (dev <= 0.0f) ? 1 : 0;
        g_nfg[t] = 0;
        g_nbg[t] = 0;
    }
}

// ---------------- K2: fused labels + pos-assign + neg-zero + norm + gather ----------------
// grid (HW/32, T), block (32, 8)
__global__ __launch_bounds__(256) void k_preprocess(const float* __restrict__ cur,
                                                    const float* __restrict__ hist,
                                                    const float* __restrict__ feat,
                                                    float* __restrict__ out)
{
    __shared__ float sf[32][260];
    __shared__ float ssp[8][32];
    __shared__ float sinv[32];
    __shared__ int   s_pos[32];
    int n0 = blockIdx.x * 32, t = blockIdx.y;
    int x = threadIdx.x, y = threadIdx.y;

    if (y == 0) {
        int n = n0 + x;
        float l = g_use[t] ? cur[t * HW + n] : hist[t * HW + n];
        out[t * HW + n] = l;
        g_neg[t][n] = 0.0f;
        int pp;
        if (l > 0.5f) pp = atomicAdd(&g_nfg[t], 1);
        else          pp = ~atomicAdd(&g_nbg[t], 1);
        s_pos[x] = pp;
    }

    const float* base = feat + (size_t)t * C_DIM * HW + n0 + x;
    float ss = 0.0f;
    #pragma unroll
    for (int cs = 0; cs < 32; cs++) {
        int c = y + cs * 8;
        float v = base[(size_t)c * HW];
        sf[x][c] = v;
        ss = fmaf(v, v, ss);
    }
    ssp[y][x] = ss;
    __syncthreads();
    if (y == 0) {
        float s = 0.0f;
        #pragma unroll
        for (int i = 0; i < 8; i++) s += ssp[i][x];
        sinv[x] = 1.0f / fmaxf(sqrtf(s), 1e-12f);
    }
    __syncthreads();

    int w = y * 32 + x;
    int nl = w >> 3, part = w & 7;
    int pp = s_pos[nl];
    __nv_bfloat16* dst = (pp >= 0) ? &g_fgH[t][pp][0] : &g_bgH[t][~pp][0];
    float inv = sinv[nl];
    #pragma unroll
    for (int q = 0; q < 4; q++) {
        int c = part * 32 + q * 8;
        float4 v0 = *(const float4*)&sf[nl][c];
        float4 v1 = *(const float4*)&sf[nl][c + 4];
        __nv_bfloat16 v[8];
        v[0] = __float2bfloat16(v0.x * inv); v[1] = __float2bfloat16(v0.y * inv);
        v[2] = __float2bfloat16(v0.z * inv); v[3] = __float2bfloat16(v0.w * inv);
        v[4] = __float2bfloat16(v1.x * inv); v[5] = __float2bfloat16(v1.y * inv);
        v[6] = __float2bfloat16(v1.z * inv); v[7] = __float2bfloat16(v1.w * inv);
        *(uint4*)&dst[c] = *(uint4*)v;
    }
}

// ---------------- K3: bf16 mma GEMM, 128x128, K-chunk 32, 3-stage (EXACT R12 body) ----------------
__global__ __launch_bounds__(256, 2) void k_gemm()
{
    int t = blockIdx.z;
    int nfg = g_nfg[t], nbg = g_nbg[t];
    int i0 = blockIdx.y * 128;
    int j0 = blockIdx.x * 128;
    if (i0 >= nfg || j0 >= nbg) return;

    __shared__ __align__(16) __nv_bfloat16 As[3][128][40];
    __shared__ __align__(16) __nv_bfloat16 Bs[3][128][40];

    const __nv_bfloat16* A = &g_fgH[t][0][0];
    const __nv_bfloat16* B = &g_bgH[t][0][0];

    int tid = threadIdx.x;
    int lane = tid & 31, wid = tid >> 5;
    int wrow = wid >> 2, wcol = wid & 3;     // 2 (m) x 4 (n) warps, 64x32 each
    int srow = tid >> 2;
    int scol = (tid & 3) * 8;

    float acc[4][4][4] = {};

    auto issue = [&](int ch, int s) {
        int k0 = ch * 32;
        #pragma unroll
        for (int h = 0; h < 2; h++) {
            int r = srow + h * 64;
            uint32_t da = (uint32_t)__cvta_generic_to_shared(&As[s][r][scol]);
            uint32_t db = (uint32_t)__cvta_generic_to_shared(&Bs[s][r][scol]);
            CP_ASYNC16(da, &A[(size_t)(i0 + r) * C_DIM + k0 + scol]);
            CP_ASYNC16(db, &B[(size_t)(j0 + r) * C_DIM + k0 + scol]);
        }
        CP_COMMIT();
    };

    issue(0, 0);
    issue(1, 1);

    #pragma unroll
    for (int ch = 0; ch < 8; ch++) {
        if (ch < 6) CP_WAIT1(); else CP_WAIT0();
        __syncthreads();
        if (ch + 2 < 8) issue(ch + 2, (ch + 2) % 3);

        int buf = ch % 3;
        #pragma unroll
        for (int ks = 0; ks < 32; ks += 16) {
            uint32_t bfr[4][2];
            #pragma unroll
            for (int p = 0; p < 2; p++) {
                int grp = lane >> 3;
                int nrow = wcol * 32 + p * 16 + ((grp >> 1) << 3) + (lane & 7);
                int ncol = ks + ((grp & 1) << 3);
                uint32_t addr = (uint32_t)__cvta_generic_to_shared(&Bs[buf][nrow][ncol]);
                asm volatile("ldmatrix.sync.aligned.m8n8.x4.shared.b16 {%0,%1,%2,%3}, [%4];"
                    : "=r"(bfr[2*p][0]), "=r"(bfr[2*p][1]),
                      "=r"(bfr[2*p+1][0]), "=r"(bfr[2*p+1][1]) : "r"(addr));
            }
            #pragma unroll
            for (int mt = 0; mt < 4; mt++) {
                int mrow = wrow * 64 + mt * 16 + (lane & 7) + ((lane >> 3) & 1) * 8;
                int mcol = ks + (lane >> 4) * 8;
                uint32_t addr = (uint32_t)__cvta_generic_to_shared(&As[buf][mrow][mcol]);
                uint32_t af[4];
                asm volatile("ldmatrix.sync.aligned.m8n8.x4.shared.b16 {%0,%1,%2,%3}, [%4];"
                    : "=r"(af[0]), "=r"(af[1]), "=r"(af[2]), "=r"(af[3]) : "r"(addr));
                #pragma unroll
                for (int nt = 0; nt < 4; nt++) {
                    asm volatile(
                        "mma.sync.aligned.m16n8k16.row.col.f32.bf16.bf16.f32 "
                        "{%0,%1,%2,%3}, {%4,%5,%6,%7}, {%8,%9}, {%0,%1,%2,%3};"
                        : "+f"(acc[mt][nt][0]), "+f"(acc[mt][nt][1]),
                          "+f"(acc[mt][nt][2]), "+f"(acc[mt][nt][3])
                        : "r"(af[0]), "r"(af[1]), "r"(af[2]), "r"(af[3]),
                          "r"(bfr[nt][0]), "r"(bfr[nt][1]));
                }
            }
        }
        __syncthreads();
    }

    // epilogue: exp + masked row sums
    int g = lane >> 2, tg = lane & 3;
    #pragma unroll
    for (int mt = 0; mt < 4; mt++) {
        float slo = 0.0f, shi = 0.0f;
        #pragma unroll
        for (int nt = 0; nt < 4; nt++) {
            int jb = j0 + wcol * 32 + nt * 8 + 2 * tg;
            if (jb < nbg)     { slo += __expf(acc[mt][nt][0] * INV_TEMP);
                                shi += __expf(acc[mt][nt][2] * INV_TEMP); }
            if (jb + 1 < nbg) { slo += __expf(acc[mt][nt][1] * INV_TEMP);
                                shi += __expf(acc[mt][nt][3] * INV_TEMP); }
        }
        slo += __shfl_xor_sync(0xffffffffu, slo, 1);
        slo += __shfl_xor_sync(0xffffffffu, slo, 2);
        shi += __shfl_xor_sync(0xffffffffu, shi, 1);
        shi += __shfl_xor_sync(0xffffffffu, shi, 2);
        if (tg == 0) {
            int i = i0 + wrow * 64 + mt * 16 + g;
            if (i < nfg)     atomicAdd(&g_neg[t][i], slo);
            if (i + 8 < nfg) atomicAdd(&g_neg[t][i + 8], shi);
        }
    }
}

// ---------------- K4: fused per-frame loss + final reduction ----------------
__global__ void k_tail(float* __restrict__ out, int loss_pos)
{
    int t = blockIdx.x, tid = threadIdx.x;
    int nfg = g_nfg[t], nbg = g_nbg[t];
    const float POS_INV = expf(-INV_TEMP);
    float local = 0.0f;
    for (int i = tid; i < nfg; i += 256)
        local += log1pf((g_neg[t][i] + EPS) * POS_INV);
    __shared__ float sh[256];
    sh[tid] = local;
    __syncthreads();
    for (int off = 128; off > 0; off >>= 1) {
        if (tid < off) sh[tid] += sh[tid + off];
        __syncthreads();
    }
    __shared__ int s_last;
    if (tid == 0) {
        float fl = sh[0] / fmaxf((float)nfg, 1.0f);
        int valid = (nfg > 0 && nbg > 0) ? 1 : 0;
        g_frame[t]  = valid ? fl : 0.0f;
        g_validf[t] = (float)valid;
        __threadfence();
        s_last = (atomicAdd(&g_done, 1) == T_FRAMES - 1);
    }
    __syncthreads();
    if (s_last && tid == 0) {
        float s = 0.0f, nv = 0.0f;
        for (int u = 0; u < T_FRAMES; u++) { s += g_frame[u]; nv += g_validf[u]; }
        out[loss_pos] = (nv > 0.0f) ? (s / fmaxf(nv, 1.0f)) : 0.0f;
    }
}

// ---------------- launch ----------------
extern "C" void kernel_launch(void* const* d_in, const int* in_sizes, int n_in,
                              void* d_out, int out_size)
{
    const float* cur  = (const float*)d_in[0];
    const float* hist = (const float*)d_in[1];
    const float* feat = (const float*)d_in[2];
    float* out = (float*)d_out;

    k_counts<<<T_FRAMES, 256>>>(cur, hist);                                       // launch 1
    k_preprocess<<<dim3(HW / 32, T_FRAMES), dim3(32, 8)>>>(cur, hist, feat, out); // launch 2
    k_gemm<<<dim3(HW / 128, HW / 128, T_FRAMES), 256>>>();                        // launch 3
    k_tail<<<T_FRAMES, 256>>>(out, out_size - 1);                                 // launch 4
}